// round 2
// baseline (speedup 1.0000x reference)
#include <cuda_runtime.h>
#include <math.h>

#define N_NODES 50000
#define N_EDGES 1600000
#define NF      128
#define EF      16
#define EFIL    32
#define CLASSES 40

// ---------------- device scratch (no allocations allowed) ----------------
__device__ int   g_is64;
__device__ float g_deg [N_NODES];
__device__ float g_dinv[N_NODES];
__device__ float g_ew  [N_EDGES];
__device__ float g_norm[N_EDGES];
__device__ int   g_row [N_EDGES];
__device__ int   g_col [N_EDGES];
__device__ float g_h1  [(size_t)N_NODES * NF];
__device__ float g_out1[(size_t)N_NODES * NF];
__device__ float g_h2  [(size_t)N_NODES * CLASSES];

// ---------------- k0: deg = 1.0 (self-loop weight) ----------------
__global__ void k_init_deg() {
    int i = blockIdx.x * blockDim.x + threadIdx.x;
    if (i < N_NODES) g_deg[i] = 1.0f;
}

// ---------------- k_detect: int32 vs int64 edge_index ----------------
// int64 with values < 50000 => every odd 32-bit word is 0.
__global__ void k_detect(const int* __restrict__ w) {
    __shared__ int any_nonzero;
    if (threadIdx.x == 0) any_nonzero = 0;
    __syncthreads();
    int v = w[2 * threadIdx.x + 1];   // 256 odd words, well within buffer
    if (v != 0) atomicOr(&any_nonzero, 1);
    __syncthreads();
    if (threadIdx.x == 0) g_is64 = (any_nonzero == 0) ? 1 : 0;
}

// ---------------- k_convert: edge_index -> int32 row/col ----------------
__global__ __launch_bounds__(256) void k_convert(const int* __restrict__ w) {
    int e = blockIdx.x * blockDim.x + threadIdx.x;
    if (e >= N_EDGES) return;
    int r, c;
    if (g_is64) {
        r = w[2 * (size_t)e];                       // low word of int64
        c = w[2 * ((size_t)N_EDGES + e)];
    } else {
        r = w[e];
        c = w[N_EDGES + e];
    }
    r = min(max(r, 0), N_NODES - 1);
    c = min(max(c, 0), N_NODES - 1);
    g_row[e] = r;
    g_col[e] = c;
}

// ---------------- k1: edge MLP -> ew, deg atomic ----------------
__global__ __launch_bounds__(256) void k_edge_mlp(
    const float* __restrict__ edge_x,
    const float* __restrict__ W1, const float* __restrict__ b1,
    const float* __restrict__ W2, const float* __restrict__ b2)
{
    __shared__ float sW1[EF * EFIL];
    __shared__ float sb1[EFIL];
    __shared__ float sW2[EFIL];
    __shared__ float sb2;
    for (int i = threadIdx.x; i < EF * EFIL; i += blockDim.x) sW1[i] = W1[i];
    if (threadIdx.x < EFIL) { sb1[threadIdx.x] = b1[threadIdx.x]; sW2[threadIdx.x] = W2[threadIdx.x]; }
    if (threadIdx.x == 0) sb2 = b2[0];
    __syncthreads();

    int e = blockIdx.x * blockDim.x + threadIdx.x;
    if (e >= N_EDGES) return;

    float xv[EF];
    const float4* ex4 = (const float4*)(edge_x + (size_t)e * EF);
#pragma unroll
    for (int q = 0; q < 4; q++) {
        float4 v = ex4[q];
        xv[q*4+0] = v.x; xv[q*4+1] = v.y; xv[q*4+2] = v.z; xv[q*4+3] = v.w;
    }

    float acc = sb2;
#pragma unroll
    for (int j = 0; j < EFIL; j++) {
        float h = sb1[j];
#pragma unroll
        for (int k = 0; k < EF; k++) h = fmaf(xv[k], sW1[k * EFIL + j], h);
        h = fmaxf(h, 0.0f);
        acc = fmaf(h, sW2[j], acc);
    }
    float w = 1.0f / (1.0f + expf(-acc));

    g_ew[e] = w;
    atomicAdd(&g_deg[g_col[e]], w);
}

// ---------------- k2: dinv = rsqrt(deg) ----------------
__global__ void k_dinv() {
    int i = blockIdx.x * blockDim.x + threadIdx.x;
    if (i < N_NODES) {
        float d = g_deg[i];
        g_dinv[i] = (d > 0.0f) ? rsqrtf(d) : 0.0f;
    }
}

// ---------------- k3: h1 = x @ Wg1; out1 = h1*dinv^2 + bg1 ----------------
__global__ __launch_bounds__(NF) void k_gemm1(
    const float* __restrict__ x,
    const float* __restrict__ Wg1,
    const float* __restrict__ bg1)
{
    __shared__ float xs[NF];
    int row = blockIdx.x;
    int t   = threadIdx.x;
    xs[t] = x[(size_t)row * NF + t];
    __syncthreads();
    float acc = 0.0f;
#pragma unroll 8
    for (int k = 0; k < NF; k++)
        acc = fmaf(xs[k], __ldg(&Wg1[k * NF + t]), acc);
    g_h1[(size_t)row * NF + t] = acc;
    float d = g_dinv[row];
    g_out1[(size_t)row * NF + t] = fmaf(acc, d * d, bg1[t]);
}

// ---------------- k4: scatter conv1 (warp per edge), store norm ----------------
__global__ __launch_bounds__(256) void k_scatter1() {
    int warp = (blockIdx.x * blockDim.x + threadIdx.x) >> 5;
    int lane = threadIdx.x & 31;
    if (warp >= N_EDGES) return;

    int r = 0, c = 0;
    float nrm = 0.0f;
    if (lane == 0) {
        r = g_row[warp];
        c = g_col[warp];
        nrm = g_dinv[r] * g_ew[warp] * g_dinv[c];
        g_norm[warp] = nrm;
    }
    r   = __shfl_sync(0xFFFFFFFFu, r, 0);
    c   = __shfl_sync(0xFFFFFFFFu, c, 0);
    nrm = __shfl_sync(0xFFFFFFFFu, nrm, 0);

    float4 hv = ((const float4*)(g_h1 + (size_t)r * NF))[lane];
    float* dst = g_out1 + (size_t)c * NF + lane * 4;
    atomicAdd(dst + 0, hv.x * nrm);
    atomicAdd(dst + 1, hv.y * nrm);
    atomicAdd(dst + 2, hv.z * nrm);
    atomicAdd(dst + 3, hv.w * nrm);
}

// ---------------- k5: h2 = relu(out1) @ Wg2; out2 = h2*dinv^2 + bg2 ----------------
__global__ __launch_bounds__(NF) void k_gemm2(
    const float* __restrict__ Wg2,
    const float* __restrict__ bg2,
    float* __restrict__ out2)
{
    __shared__ float xs[NF];
    int row = blockIdx.x;
    int t   = threadIdx.x;
    float v = g_out1[(size_t)row * NF + t];
    xs[t] = (v > 0.0f) ? v : 0.0f;
    __syncthreads();
    if (t < CLASSES) {
        float acc = 0.0f;
#pragma unroll 8
        for (int k = 0; k < NF; k++)
            acc = fmaf(xs[k], __ldg(&Wg2[k * CLASSES + t]), acc);
        g_h2[(size_t)row * CLASSES + t] = acc;
        float d = g_dinv[row];
        out2[(size_t)row * CLASSES + t] = fmaf(acc, d * d, bg2[t]);
    }
}

// ---------------- k6: scatter conv2 (warp per edge, 40 feats) ----------------
__global__ __launch_bounds__(256) void k_scatter2(float* __restrict__ out2) {
    int warp = (blockIdx.x * blockDim.x + threadIdx.x) >> 5;
    int lane = threadIdx.x & 31;
    if (warp >= N_EDGES) return;

    int r = 0, c = 0;
    float nrm = 0.0f;
    if (lane == 0) {
        r = g_row[warp];
        c = g_col[warp];
        nrm = g_norm[warp];
    }
    r   = __shfl_sync(0xFFFFFFFFu, r, 0);
    c   = __shfl_sync(0xFFFFFFFFu, c, 0);
    nrm = __shfl_sync(0xFFFFFFFFu, nrm, 0);

    const float* hs = g_h2 + (size_t)r * CLASSES;
    float* dst = out2 + (size_t)c * CLASSES;
    atomicAdd(dst + lane, hs[lane] * nrm);
    if (lane < CLASSES - 32)
        atomicAdd(dst + 32 + lane, hs[32 + lane] * nrm);
}

// ---------------- launch ----------------
extern "C" void kernel_launch(void* const* d_in, const int* in_sizes, int n_in,
                              void* d_out, int out_size)
{
    const float* x      = (const float*)d_in[0];
    const int*   eidx   = (const int*)d_in[1];      // int32 or int64 words — detected on device
    const float* edge_x = (const float*)d_in[2];
    const float* W1     = (const float*)d_in[3];
    const float* b1     = (const float*)d_in[4];
    const float* W2     = (const float*)d_in[5];
    const float* b2     = (const float*)d_in[6];
    const float* Wg1    = (const float*)d_in[7];
    const float* bg1    = (const float*)d_in[8];
    const float* Wg2    = (const float*)d_in[9];
    const float* bg2    = (const float*)d_in[10];
    float*       out2   = (float*)d_out;

    k_init_deg<<<(N_NODES + 255) / 256, 256>>>();
    k_detect<<<1, 256>>>(eidx);
    k_convert<<<(N_EDGES + 255) / 256, 256>>>(eidx);
    k_edge_mlp<<<(N_EDGES + 255) / 256, 256>>>(edge_x, W1, b1, W2, b2);
    k_dinv<<<(N_NODES + 255) / 256, 256>>>();
    k_gemm1<<<N_NODES, NF>>>(x, Wg1, bg1);
    k_scatter1<<<(N_EDGES * 32 + 255) / 256, 256>>>();
    k_gemm2<<<N_NODES, NF>>>(Wg2, bg2, out2);
    k_scatter2<<<(N_EDGES * 32 + 255) / 256, 256>>>(out2);
}

// round 3
// speedup vs baseline: 2.2506x; 2.2506x over previous
#include <cuda_runtime.h>
#include <math.h>

#define N_NODES 50000
#define N_EDGES 1600000
#define NF      128
#define EF      16
#define EFIL    32
#define CLASSES 40

// ---------------- device scratch (no allocations allowed) ----------------
__device__ int   g_is64;
__device__ float g_deg [N_NODES];
__device__ float g_dinv[N_NODES];
__device__ float g_ew  [N_EDGES];
__device__ float g_norm[N_EDGES];
__device__ int   g_row [N_EDGES];
__device__ int   g_col [N_EDGES];
__device__ float g_h1  [(size_t)N_NODES * NF];
__device__ float g_out1[(size_t)N_NODES * NF];
__device__ float g_h2  [(size_t)N_NODES * CLASSES];

// vectorized no-return global reduction (sm_90+)
__device__ __forceinline__ void red_add_v4(float* p, float a, float b, float c, float d) {
    asm volatile("red.global.add.v4.f32 [%0], {%1, %2, %3, %4};"
                 :: "l"(p), "f"(a), "f"(b), "f"(c), "f"(d) : "memory");
}

// ---------------- k0: deg = 1.0 (self-loop weight) ----------------
__global__ void k_init_deg() {
    int i = blockIdx.x * blockDim.x + threadIdx.x;
    if (i < N_NODES) g_deg[i] = 1.0f;
}

// ---------------- k_detect: int32 vs int64 edge_index ----------------
__global__ void k_detect(const int* __restrict__ w) {
    __shared__ int any_nonzero;
    if (threadIdx.x == 0) any_nonzero = 0;
    __syncthreads();
    int v = w[2 * threadIdx.x + 1];
    if (v != 0) atomicOr(&any_nonzero, 1);
    __syncthreads();
    if (threadIdx.x == 0) g_is64 = (any_nonzero == 0) ? 1 : 0;
}

// ---------------- k1: edge MLP (+ idx convert) -> ew, row, col, deg ----------------
__global__ __launch_bounds__(256) void k_edge_mlp(
    const float* __restrict__ edge_x,
    const int*   __restrict__ eidx,
    const float* __restrict__ W1, const float* __restrict__ b1,
    const float* __restrict__ W2, const float* __restrict__ b2)
{
    __shared__ float4 sW1[EF * 8];   // W1[k][4j..4j+3]
    __shared__ float4 sb1[8];
    __shared__ float4 sW2[8];
    __shared__ float  sb2;
    for (int i = threadIdx.x; i < EF * 8; i += blockDim.x)
        sW1[i] = ((const float4*)W1)[i];
    if (threadIdx.x < 8) {
        sb1[threadIdx.x] = ((const float4*)b1)[threadIdx.x];
        sW2[threadIdx.x] = ((const float4*)W2)[threadIdx.x];
    }
    if (threadIdx.x == 0) sb2 = b2[0];
    __syncthreads();

    int e = blockIdx.x * blockDim.x + threadIdx.x;
    if (e >= N_EDGES) return;

    float xv[EF];
    const float4* ex4 = (const float4*)(edge_x + (size_t)e * EF);
#pragma unroll
    for (int q = 0; q < 4; q++) {
        float4 v = ex4[q];
        xv[q*4+0] = v.x; xv[q*4+1] = v.y; xv[q*4+2] = v.z; xv[q*4+3] = v.w;
    }

    float4 h[8];
#pragma unroll
    for (int j = 0; j < 8; j++) h[j] = sb1[j];
#pragma unroll
    for (int k = 0; k < EF; k++) {
        float xk = xv[k];
#pragma unroll
        for (int j = 0; j < 8; j++) {
            float4 w = sW1[k * 8 + j];
            h[j].x = fmaf(xk, w.x, h[j].x);
            h[j].y = fmaf(xk, w.y, h[j].y);
            h[j].z = fmaf(xk, w.z, h[j].z);
            h[j].w = fmaf(xk, w.w, h[j].w);
        }
    }
    float acc = sb2;
#pragma unroll
    for (int j = 0; j < 8; j++) {
        float4 w = sW2[j];
        acc = fmaf(fmaxf(h[j].x, 0.0f), w.x, acc);
        acc = fmaf(fmaxf(h[j].y, 0.0f), w.y, acc);
        acc = fmaf(fmaxf(h[j].z, 0.0f), w.z, acc);
        acc = fmaf(fmaxf(h[j].w, 0.0f), w.w, acc);
    }
    float w = 1.0f / (1.0f + __expf(-acc));

    int r, c;
    if (g_is64) {
        r = eidx[2 * (size_t)e];
        c = eidx[2 * ((size_t)N_EDGES + e)];
    } else {
        r = eidx[e];
        c = eidx[N_EDGES + e];
    }
    r = min(max(r, 0), N_NODES - 1);
    c = min(max(c, 0), N_NODES - 1);
    g_row[e] = r;
    g_col[e] = c;
    g_ew[e]  = w;
    atomicAdd(&g_deg[c], w);
}

// ---------------- k2: dinv = rsqrt(deg) ----------------
__global__ void k_dinv() {
    int i = blockIdx.x * blockDim.x + threadIdx.x;
    if (i < N_NODES) {
        float d = g_deg[i];
        g_dinv[i] = (d > 0.0f) ? rsqrtf(d) : 0.0f;
    }
}

// ---------------- k3: tiled gemm1: h1 = x@Wg1; out1 = h1*dinv^2 + bg1 ----------------
// 64 rows/block, 8 warps, warp = 8 rows, lane = 4 cols.
#define G1_ROWS 64
__global__ __launch_bounds__(256) void k_gemm1(
    const float* __restrict__ x,
    const float* __restrict__ Wg1,
    const float* __restrict__ bg1)
{
    __shared__ float4 xs[G1_ROWS * 32];            // 64 rows x 128 floats
    int base = blockIdx.x * G1_ROWS;
    int tid  = threadIdx.x;

    // cooperative load of 64 rows (zero-pad the tail)
    const float4* xg = (const float4*)(x + (size_t)base * NF);
    int total4 = G1_ROWS * 32;
    int valid4 = (N_NODES - base) * 32;            // may exceed total4
#pragma unroll
    for (int i = 0; i < total4 / 256; i++) {
        int idx = tid + i * 256;
        xs[idx] = (idx < valid4) ? xg[idx] : make_float4(0.f, 0.f, 0.f, 0.f);
    }
    __syncthreads();

    int warp = tid >> 5, lane = tid & 31;
    int r0 = warp * 8;                             // 8 rows per warp
    const float4* Wv = (const float4*)Wg1;         // [k][32] float4

    float4 acc[8];
#pragma unroll
    for (int r = 0; r < 8; r++) acc[r] = make_float4(0.f, 0.f, 0.f, 0.f);

    for (int kt = 0; kt < 32; kt++) {
        float4 w0 = __ldg(&Wv[(kt*4 + 0) * 32 + lane]);
        float4 w1 = __ldg(&Wv[(kt*4 + 1) * 32 + lane]);
        float4 w2 = __ldg(&Wv[(kt*4 + 2) * 32 + lane]);
        float4 w3 = __ldg(&Wv[(kt*4 + 3) * 32 + lane]);
#pragma unroll
        for (int r = 0; r < 8; r++) {
            float4 xv = xs[(r0 + r) * 32 + kt];
            acc[r].x = fmaf(xv.x, w0.x, acc[r].x); acc[r].y = fmaf(xv.x, w0.y, acc[r].y);
            acc[r].z = fmaf(xv.x, w0.z, acc[r].z); acc[r].w = fmaf(xv.x, w0.w, acc[r].w);
            acc[r].x = fmaf(xv.y, w1.x, acc[r].x); acc[r].y = fmaf(xv.y, w1.y, acc[r].y);
            acc[r].z = fmaf(xv.y, w1.z, acc[r].z); acc[r].w = fmaf(xv.y, w1.w, acc[r].w);
            acc[r].x = fmaf(xv.z, w2.x, acc[r].x); acc[r].y = fmaf(xv.z, w2.y, acc[r].y);
            acc[r].z = fmaf(xv.z, w2.z, acc[r].z); acc[r].w = fmaf(xv.z, w2.w, acc[r].w);
            acc[r].x = fmaf(xv.w, w3.x, acc[r].x); acc[r].y = fmaf(xv.w, w3.y, acc[r].y);
            acc[r].z = fmaf(xv.w, w3.z, acc[r].z); acc[r].w = fmaf(xv.w, w3.w, acc[r].w);
        }
    }

    float4 bv = __ldg(&((const float4*)bg1)[lane]);
#pragma unroll
    for (int r = 0; r < 8; r++) {
        int row = base + r0 + r;
        if (row < N_NODES) {
            float d = g_dinv[row];
            float dd = d * d;
            ((float4*)(g_h1 + (size_t)row * NF))[lane] = acc[r];
            float4 o;
            o.x = fmaf(acc[r].x, dd, bv.x);
            o.y = fmaf(acc[r].y, dd, bv.y);
            o.z = fmaf(acc[r].z, dd, bv.z);
            o.w = fmaf(acc[r].w, dd, bv.w);
            ((float4*)(g_out1 + (size_t)row * NF))[lane] = o;
        }
    }
}

// ---------------- k4: scatter conv1 (warp/edge, vector red), store norm ----------------
__global__ __launch_bounds__(256) void k_scatter1() {
    int warp = (blockIdx.x * blockDim.x + threadIdx.x) >> 5;
    int lane = threadIdx.x & 31;
    if (warp >= N_EDGES) return;

    int r = 0, c = 0;
    float nrm = 0.0f;
    if (lane == 0) {
        r = g_row[warp];
        c = g_col[warp];
        nrm = g_dinv[r] * g_ew[warp] * g_dinv[c];
        g_norm[warp] = nrm;
    }
    r   = __shfl_sync(0xFFFFFFFFu, r, 0);
    c   = __shfl_sync(0xFFFFFFFFu, c, 0);
    nrm = __shfl_sync(0xFFFFFFFFu, nrm, 0);

    float4 hv = __ldg(&((const float4*)(g_h1 + (size_t)r * NF))[lane]);
    float* dst = g_out1 + (size_t)c * NF + lane * 4;
    red_add_v4(dst, hv.x * nrm, hv.y * nrm, hv.z * nrm, hv.w * nrm);
}

// ---------------- k5: gemm2: h2 = relu(out1)@Wg2; out2 = h2*dinv^2 + bg2 ----------------
// 8 rows per block, 40 threads, thread = 1 col x 8 rows.
__global__ __launch_bounds__(40) void k_gemm2(
    const float* __restrict__ Wg2,
    const float* __restrict__ bg2,
    float* __restrict__ out2)
{
    __shared__ float4 xs[8 * 32];                  // 8 rows x 128 relu'd floats
    int base = blockIdx.x * 8;
    int t = threadIdx.x;

    for (int i = t; i < 8 * 32; i += 40) {
        float4 v = ((const float4*)(g_out1 + (size_t)base * NF))[i];
        v.x = fmaxf(v.x, 0.f); v.y = fmaxf(v.y, 0.f);
        v.z = fmaxf(v.z, 0.f); v.w = fmaxf(v.w, 0.f);
        xs[i] = v;
    }
    __syncthreads();

    float acc[8];
#pragma unroll
    for (int r = 0; r < 8; r++) acc[r] = 0.f;

    for (int kt = 0; kt < 32; kt++) {
        float w0 = __ldg(&Wg2[(kt*4 + 0) * CLASSES + t]);
        float w1 = __ldg(&Wg2[(kt*4 + 1) * CLASSES + t]);
        float w2 = __ldg(&Wg2[(kt*4 + 2) * CLASSES + t]);
        float w3 = __ldg(&Wg2[(kt*4 + 3) * CLASSES + t]);
#pragma unroll
        for (int r = 0; r < 8; r++) {
            float4 xv = xs[r * 32 + kt];
            acc[r] = fmaf(xv.x, w0, acc[r]);
            acc[r] = fmaf(xv.y, w1, acc[r]);
            acc[r] = fmaf(xv.z, w2, acc[r]);
            acc[r] = fmaf(xv.w, w3, acc[r]);
        }
    }

    float b = __ldg(&bg2[t]);
#pragma unroll
    for (int r = 0; r < 8; r++) {
        int row = base + r;
        float d = g_dinv[row];
        g_h2[(size_t)row * CLASSES + t] = acc[r];
        out2[(size_t)row * CLASSES + t] = fmaf(acc[r], d * d, b);
    }
}

// ---------------- k6: scatter conv2 (3 edges/warp, 10 lanes x float4) ----------------
__global__ __launch_bounds__(256) void k_scatter2(float* __restrict__ out2) {
    int warp = (blockIdx.x * blockDim.x + threadIdx.x) >> 5;
    int lane = threadIdx.x & 31;
    int e = warp * 3 + lane / 10;
    int q = lane % 10;
    if (lane >= 30 || e >= N_EDGES) return;

    int r = g_row[e];
    int c = g_col[e];
    float nrm = g_norm[e];

    float4 hv = __ldg((const float4*)(g_h2 + (size_t)r * CLASSES + q * 4));
    float* dst = out2 + (size_t)c * CLASSES + q * 4;
    red_add_v4(dst, hv.x * nrm, hv.y * nrm, hv.z * nrm, hv.w * nrm);
}

// ---------------- launch ----------------
extern "C" void kernel_launch(void* const* d_in, const int* in_sizes, int n_in,
                              void* d_out, int out_size)
{
    const float* x      = (const float*)d_in[0];
    const int*   eidx   = (const int*)d_in[1];
    const float* edge_x = (const float*)d_in[2];
    const float* W1     = (const float*)d_in[3];
    const float* b1     = (const float*)d_in[4];
    const float* W2     = (const float*)d_in[5];
    const float* b2     = (const float*)d_in[6];
    const float* Wg1    = (const float*)d_in[7];
    const float* bg1    = (const float*)d_in[8];
    const float* Wg2    = (const float*)d_in[9];
    const float* bg2    = (const float*)d_in[10];
    float*       out2   = (float*)d_out;

    k_init_deg<<<(N_NODES + 255) / 256, 256>>>();
    k_detect<<<1, 256>>>(eidx);
    k_edge_mlp<<<(N_EDGES + 255) / 256, 256>>>(edge_x, eidx, W1, b1, W2, b2);
    k_dinv<<<(N_NODES + 255) / 256, 256>>>();
    k_gemm1<<<(N_NODES + G1_ROWS - 1) / G1_ROWS, 256>>>(x, Wg1, bg1);
    k_scatter1<<<(N_EDGES * 32 + 255) / 256, 256>>>();
    k_gemm2<<<N_NODES / 8, 40>>>(Wg2, bg2, out2);
    int w2 = (N_EDGES + 2) / 3;
    k_scatter2<<<(w2 * 32 + 255) / 256, 256>>>(out2);
}

// round 4
// speedup vs baseline: 3.4302x; 1.5241x over previous
#include <cuda_runtime.h>
#include <math.h>

#define N_NODES 50000
#define N_EDGES 1600000
#define NF      128
#define EF      16
#define EFIL    32
#define CLASSES 40
#define CAP     128   // per-node in-edge bucket capacity (Poisson(32); P(>128) ~ 1e-35)

// ---------------- device scratch (no allocations allowed) ----------------
__device__ int   g_is64;
__device__ float g_deg [N_NODES];
__device__ float g_dinv[N_NODES];
__device__ int   g_cnt [N_NODES];
__device__ int2  g_slot[(size_t)N_NODES * CAP];   // (src, weight-bits) then (src, norm-bits)
__device__ float g_h1  [(size_t)N_NODES * NF];
__device__ float g_out1[(size_t)N_NODES * NF];
__device__ float g_h2  [(size_t)N_NODES * CLASSES];

// ---------------- k0: deg = 1 (self-loop), cnt = 0 ----------------
__global__ void k_init() {
    int i = blockIdx.x * blockDim.x + threadIdx.x;
    if (i < N_NODES) { g_deg[i] = 1.0f; g_cnt[i] = 0; }
}

// ---------------- k_detect: int32 vs int64 edge_index ----------------
__global__ void k_detect(const int* __restrict__ w) {
    __shared__ int any_nonzero;
    if (threadIdx.x == 0) any_nonzero = 0;
    __syncthreads();
    int v = w[2 * threadIdx.x + 1];
    if (v != 0) atomicOr(&any_nonzero, 1);
    __syncthreads();
    if (threadIdx.x == 0) g_is64 = (any_nonzero == 0) ? 1 : 0;
}

// ---------------- k1: edge MLP -> weight, bucket fill, deg ----------------
__global__ __launch_bounds__(256) void k_edge_mlp(
    const float* __restrict__ edge_x,
    const int*   __restrict__ eidx,
    const float* __restrict__ W1, const float* __restrict__ b1,
    const float* __restrict__ W2, const float* __restrict__ b2)
{
    __shared__ float4 sW1[EF * 8];
    __shared__ float4 sb1[8];
    __shared__ float4 sW2[8];
    __shared__ float  sb2;
    for (int i = threadIdx.x; i < EF * 8; i += blockDim.x)
        sW1[i] = ((const float4*)W1)[i];
    if (threadIdx.x < 8) {
        sb1[threadIdx.x] = ((const float4*)b1)[threadIdx.x];
        sW2[threadIdx.x] = ((const float4*)W2)[threadIdx.x];
    }
    if (threadIdx.x == 0) sb2 = b2[0];
    __syncthreads();

    int e = blockIdx.x * blockDim.x + threadIdx.x;
    if (e >= N_EDGES) return;

    float xv[EF];
    const float4* ex4 = (const float4*)(edge_x + (size_t)e * EF);
#pragma unroll
    for (int q = 0; q < 4; q++) {
        float4 v = ex4[q];
        xv[q*4+0] = v.x; xv[q*4+1] = v.y; xv[q*4+2] = v.z; xv[q*4+3] = v.w;
    }

    float4 h[8];
#pragma unroll
    for (int j = 0; j < 8; j++) h[j] = sb1[j];
#pragma unroll
    for (int k = 0; k < EF; k++) {
        float xk = xv[k];
#pragma unroll
        for (int j = 0; j < 8; j++) {
            float4 w = sW1[k * 8 + j];
            h[j].x = fmaf(xk, w.x, h[j].x);
            h[j].y = fmaf(xk, w.y, h[j].y);
            h[j].z = fmaf(xk, w.z, h[j].z);
            h[j].w = fmaf(xk, w.w, h[j].w);
        }
    }
    float acc = sb2;
#pragma unroll
    for (int j = 0; j < 8; j++) {
        float4 w = sW2[j];
        acc = fmaf(fmaxf(h[j].x, 0.0f), w.x, acc);
        acc = fmaf(fmaxf(h[j].y, 0.0f), w.y, acc);
        acc = fmaf(fmaxf(h[j].z, 0.0f), w.z, acc);
        acc = fmaf(fmaxf(h[j].w, 0.0f), w.w, acc);
    }
    float w = 1.0f / (1.0f + __expf(-acc));

    int r, c;
    if (g_is64) {
        r = eidx[2 * (size_t)e];
        c = eidx[2 * ((size_t)N_EDGES + e)];
    } else {
        r = eidx[e];
        c = eidx[N_EDGES + e];
    }
    r = min(max(r, 0), N_NODES - 1);
    c = min(max(c, 0), N_NODES - 1);

    int pos = atomicAdd(&g_cnt[c], 1);
    if (pos < CAP) g_slot[(size_t)c * CAP + pos] = make_int2(r, __float_as_int(w));
    atomicAdd(&g_deg[c], w);
}

// ---------------- k2: dinv = rsqrt(deg) ----------------
__global__ void k_dinv() {
    int i = blockIdx.x * blockDim.x + threadIdx.x;
    if (i < N_NODES) {
        float d = g_deg[i];
        g_dinv[i] = (d > 0.0f) ? rsqrtf(d) : 0.0f;
    }
}

// ---------------- k_norm: slot weight -> final norm (warp per node) ----------------
__global__ __launch_bounds__(256) void k_norm() {
    int node = (blockIdx.x * blockDim.x + threadIdx.x) >> 5;
    int lane = threadIdx.x & 31;
    if (node >= N_NODES) return;
    int cnt = min(g_cnt[node], CAP);
    float dc = g_dinv[node];
    int2* sl = g_slot + (size_t)node * CAP;
    for (int i = lane; i < cnt; i += 32) {
        int2 p = sl[i];
        float nrm = g_dinv[p.x] * __int_as_float(p.y) * dc;
        sl[i].y = __float_as_int(nrm);
    }
}

// ---------------- k3: tiled gemm1: h1 = x @ Wg1 ----------------
#define G1_ROWS 64
__global__ __launch_bounds__(256) void k_gemm1(
    const float* __restrict__ x,
    const float* __restrict__ Wg1)
{
    __shared__ float4 xs[G1_ROWS * 32];
    int base = blockIdx.x * G1_ROWS;
    int tid  = threadIdx.x;

    const float4* xg = (const float4*)(x + (size_t)base * NF);
    int valid4 = (N_NODES - base) * 32;
#pragma unroll
    for (int i = 0; i < (G1_ROWS * 32) / 256; i++) {
        int idx = tid + i * 256;
        xs[idx] = (idx < valid4) ? xg[idx] : make_float4(0.f, 0.f, 0.f, 0.f);
    }
    __syncthreads();

    int warp = tid >> 5, lane = tid & 31;
    int r0 = warp * 8;
    const float4* Wv = (const float4*)Wg1;

    float4 acc[8];
#pragma unroll
    for (int r = 0; r < 8; r++) acc[r] = make_float4(0.f, 0.f, 0.f, 0.f);

    for (int kt = 0; kt < 32; kt++) {
        float4 w0 = __ldg(&Wv[(kt*4 + 0) * 32 + lane]);
        float4 w1 = __ldg(&Wv[(kt*4 + 1) * 32 + lane]);
        float4 w2 = __ldg(&Wv[(kt*4 + 2) * 32 + lane]);
        float4 w3 = __ldg(&Wv[(kt*4 + 3) * 32 + lane]);
#pragma unroll
        for (int r = 0; r < 8; r++) {
            float4 xv = xs[(r0 + r) * 32 + kt];
            acc[r].x = fmaf(xv.x, w0.x, acc[r].x); acc[r].y = fmaf(xv.x, w0.y, acc[r].y);
            acc[r].z = fmaf(xv.x, w0.z, acc[r].z); acc[r].w = fmaf(xv.x, w0.w, acc[r].w);
            acc[r].x = fmaf(xv.y, w1.x, acc[r].x); acc[r].y = fmaf(xv.y, w1.y, acc[r].y);
            acc[r].z = fmaf(xv.y, w1.z, acc[r].z); acc[r].w = fmaf(xv.y, w1.w, acc[r].w);
            acc[r].x = fmaf(xv.z, w2.x, acc[r].x); acc[r].y = fmaf(xv.z, w2.y, acc[r].y);
            acc[r].z = fmaf(xv.z, w2.z, acc[r].z); acc[r].w = fmaf(xv.z, w2.w, acc[r].w);
            acc[r].x = fmaf(xv.w, w3.x, acc[r].x); acc[r].y = fmaf(xv.w, w3.y, acc[r].y);
            acc[r].z = fmaf(xv.w, w3.z, acc[r].z); acc[r].w = fmaf(xv.w, w3.w, acc[r].w);
        }
    }

#pragma unroll
    for (int r = 0; r < 8; r++) {
        int row = base + r0 + r;
        if (row < N_NODES)
            ((float4*)(g_h1 + (size_t)row * NF))[lane] = acc[r];
    }
}

// ---------------- k4: gather conv1 (warp per node) ----------------
__global__ __launch_bounds__(256) void k_gather1(const float* __restrict__ bg1) {
    int c    = (blockIdx.x * blockDim.x + threadIdx.x) >> 5;
    int lane = threadIdx.x & 31;
    if (c >= N_NODES) return;

    int   cnt = min(g_cnt[c], CAP);
    float dd  = 1.0f / g_deg[c];        // dinv[c]^2 for the self-loop

    float4 acc = __ldg(&((const float4*)bg1)[lane]);
    float4 hc  = ((const float4*)(g_h1 + (size_t)c * NF))[lane];
    acc.x = fmaf(hc.x, dd, acc.x); acc.y = fmaf(hc.y, dd, acc.y);
    acc.z = fmaf(hc.z, dd, acc.z); acc.w = fmaf(hc.w, dd, acc.w);

    const int2* sl = g_slot + (size_t)c * CAP;
    int base = 0;
    for (; base + 32 <= cnt; base += 32) {
        int2 p = sl[base + lane];
#pragma unroll 8
        for (int j = 0; j < 32; j++) {
            int   src = __shfl_sync(0xFFFFFFFFu, p.x, j);
            float nrm = __int_as_float(__shfl_sync(0xFFFFFFFFu, p.y, j));
            float4 hv = __ldg(&((const float4*)(g_h1 + (size_t)src * NF))[lane]);
            acc.x = fmaf(hv.x, nrm, acc.x); acc.y = fmaf(hv.y, nrm, acc.y);
            acc.z = fmaf(hv.z, nrm, acc.z); acc.w = fmaf(hv.w, nrm, acc.w);
        }
    }
    if (base < cnt) {
        int2 p = (base + lane < cnt) ? sl[base + lane] : make_int2(0, 0);
        int  m = cnt - base;
        for (int j = 0; j < m; j++) {
            int   src = __shfl_sync(0xFFFFFFFFu, p.x, j);
            float nrm = __int_as_float(__shfl_sync(0xFFFFFFFFu, p.y, j));
            float4 hv = __ldg(&((const float4*)(g_h1 + (size_t)src * NF))[lane]);
            acc.x = fmaf(hv.x, nrm, acc.x); acc.y = fmaf(hv.y, nrm, acc.y);
            acc.z = fmaf(hv.z, nrm, acc.z); acc.w = fmaf(hv.w, nrm, acc.w);
        }
    }
    ((float4*)(g_out1 + (size_t)c * NF))[lane] = acc;
}

// ---------------- k5: gemm2: h2 = relu(out1) @ Wg2 ----------------
// 256-thread block, 6 groups of 40 threads, each group does 8 rows (48 rows/block)
#define G2_ROWS 48
__global__ __launch_bounds__(256) void k_gemm2(const float* __restrict__ Wg2) {
    __shared__ float4 xs[G2_ROWS * 32];
    int base = blockIdx.x * G2_ROWS;
    int tid  = threadIdx.x;

    const float4* xg = (const float4*)(g_out1 + (size_t)base * NF);
    int valid4 = (N_NODES - base) * 32;
    for (int i = tid; i < G2_ROWS * 32; i += 256) {
        float4 v = (i < valid4) ? xg[i] : make_float4(0.f, 0.f, 0.f, 0.f);
        v.x = fmaxf(v.x, 0.f); v.y = fmaxf(v.y, 0.f);
        v.z = fmaxf(v.z, 0.f); v.w = fmaxf(v.w, 0.f);
        xs[i] = v;
    }
    __syncthreads();

    if (tid >= 240) return;
    int grp = tid / 40;          // 0..5
    int t   = tid % 40;          // output column
    int r0  = grp * 8;

    float acc[8];
#pragma unroll
    for (int r = 0; r < 8; r++) acc[r] = 0.f;

    for (int kt = 0; kt < 32; kt++) {
        float w0 = __ldg(&Wg2[(kt*4 + 0) * CLASSES + t]);
        float w1 = __ldg(&Wg2[(kt*4 + 1) * CLASSES + t]);
        float w2 = __ldg(&Wg2[(kt*4 + 2) * CLASSES + t]);
        float w3 = __ldg(&Wg2[(kt*4 + 3) * CLASSES + t]);
#pragma unroll
        for (int r = 0; r < 8; r++) {
            float4 xv = xs[(r0 + r) * 32 + kt];
            acc[r] = fmaf(xv.x, w0, acc[r]);
            acc[r] = fmaf(xv.y, w1, acc[r]);
            acc[r] = fmaf(xv.z, w2, acc[r]);
            acc[r] = fmaf(xv.w, w3, acc[r]);
        }
    }

#pragma unroll
    for (int r = 0; r < 8; r++) {
        int row = base + r0 + r;
        if (row < N_NODES)
            g_h2[(size_t)row * CLASSES + t] = acc[r];
    }
}

// ---------------- k6: gather conv2 (warp per node, 40 feats) ----------------
__global__ __launch_bounds__(256) void k_gather2(
    const float* __restrict__ bg2, float* __restrict__ out2)
{
    int c    = (blockIdx.x * blockDim.x + threadIdx.x) >> 5;
    int lane = threadIdx.x & 31;
    if (c >= N_NODES) return;

    int   cnt = min(g_cnt[c], CAP);
    float dd  = 1.0f / g_deg[c];

    float acc0 = __ldg(&bg2[lane]);
    float acc1 = (lane < 8) ? __ldg(&bg2[32 + lane]) : 0.f;
    {
        const float* hc = g_h2 + (size_t)c * CLASSES;
        acc0 = fmaf(hc[lane], dd, acc0);
        if (lane < 8) acc1 = fmaf(hc[32 + lane], dd, acc1);
    }

    const int2* sl = g_slot + (size_t)c * CAP;
    int base = 0;
    for (; base + 32 <= cnt; base += 32) {
        int2 p = sl[base + lane];
#pragma unroll 8
        for (int j = 0; j < 32; j++) {
            int   src = __shfl_sync(0xFFFFFFFFu, p.x, j);
            float nrm = __int_as_float(__shfl_sync(0xFFFFFFFFu, p.y, j));
            const float* hs = g_h2 + (size_t)src * CLASSES;
            acc0 = fmaf(__ldg(&hs[lane]), nrm, acc0);
            if (lane < 8) acc1 = fmaf(__ldg(&hs[32 + lane]), nrm, acc1);
        }
    }
    if (base < cnt) {
        int2 p = (base + lane < cnt) ? sl[base + lane] : make_int2(0, 0);
        int  m = cnt - base;
        for (int j = 0; j < m; j++) {
            int   src = __shfl_sync(0xFFFFFFFFu, p.x, j);
            float nrm = __int_as_float(__shfl_sync(0xFFFFFFFFu, p.y, j));
            const float* hs = g_h2 + (size_t)src * CLASSES;
            acc0 = fmaf(__ldg(&hs[lane]), nrm, acc0);
            if (lane < 8) acc1 = fmaf(__ldg(&hs[32 + lane]), nrm, acc1);
        }
    }
    out2[(size_t)c * CLASSES + lane] = acc0;
    if (lane < 8) out2[(size_t)c * CLASSES + 32 + lane] = acc1;
}

// ---------------- launch ----------------
extern "C" void kernel_launch(void* const* d_in, const int* in_sizes, int n_in,
                              void* d_out, int out_size)
{
    const float* x      = (const float*)d_in[0];
    const int*   eidx   = (const int*)d_in[1];
    const float* edge_x = (const float*)d_in[2];
    const float* W1     = (const float*)d_in[3];
    const float* b1     = (const float*)d_in[4];
    const float* W2     = (const float*)d_in[5];
    const float* b2     = (const float*)d_in[6];
    const float* Wg1    = (const float*)d_in[7];
    const float* bg1    = (const float*)d_in[8];
    const float* Wg2    = (const float*)d_in[9];
    const float* bg2    = (const float*)d_in[10];
    float*       out2   = (float*)d_out;

    k_init  <<<(N_NODES + 255) / 256, 256>>>();
    k_detect<<<1, 256>>>(eidx);
    k_edge_mlp<<<(N_EDGES + 255) / 256, 256>>>(edge_x, eidx, W1, b1, W2, b2);
    k_dinv  <<<(N_NODES + 255) / 256, 256>>>();
    k_norm  <<<(N_NODES * 32 + 255) / 256, 256>>>();
    k_gemm1 <<<(N_NODES + G1_ROWS - 1) / G1_ROWS, 256>>>(x, Wg1);
    k_gather1<<<(N_NODES * 32 + 255) / 256, 256>>>(bg1);
    k_gemm2 <<<(N_NODES + G2_ROWS - 1) / G2_ROWS, 256>>>(Wg2);
    k_gather2<<<(N_NODES * 32 + 255) / 256, 256>>>(bg2, out2);
}

// round 5
// speedup vs baseline: 3.7749x; 1.1005x over previous
#include <cuda_runtime.h>
#include <cuda_fp16.h>
#include <math.h>

#define N_NODES 50000
#define N_EDGES 1600000
#define NF      128
#define EF      16
#define EFIL    32
#define CLASSES 40
#define CAP     128   // per-node in-edge bucket capacity (Poisson(32); P(>128) ~ 1e-35)

// ---------------- device scratch (no allocations allowed) ----------------
__device__ int    g_is64;
__device__ float  g_deg [N_NODES];
__device__ float  g_dinv[N_NODES];
__device__ int    g_cnt [N_NODES];
__device__ int2   g_slot[(size_t)N_NODES * CAP];  // (src, w-bits) -> (src, norm-bits)
__device__ __half g_h1h [(size_t)N_NODES * NF];   // fp16 messages, layer 1
__device__ float  g_out1[(size_t)N_NODES * NF];
__device__ __half g_h2h [(size_t)N_NODES * CLASSES];

// ---------------- k0: deg=1, cnt=0, + int32/int64 detect (block 0) ----------------
__global__ void k_init_detect(const int* __restrict__ w) {
    int i = blockIdx.x * blockDim.x + threadIdx.x;
    if (i < N_NODES) { g_deg[i] = 1.0f; g_cnt[i] = 0; }
    if (blockIdx.x == 0) {
        __shared__ int any_nonzero;
        if (threadIdx.x == 0) any_nonzero = 0;
        __syncthreads();
        if (w[2 * threadIdx.x + 1] != 0) atomicOr(&any_nonzero, 1);
        __syncthreads();
        if (threadIdx.x == 0) g_is64 = (any_nonzero == 0) ? 1 : 0;
    }
}

// ---------------- k1: fused [gemm1 | edge MLP] by block range ----------------
#define G1_ROWS   64
#define G1_BLOCKS ((N_NODES + G1_ROWS - 1) / G1_ROWS)          // 782
#define MLP_BLOCKS ((N_EDGES + 255) / 256)                     // 6250

__global__ __launch_bounds__(256) void k_mlp_gemm1(
    const float* __restrict__ edge_x,
    const int*   __restrict__ eidx,
    const float* __restrict__ W1, const float* __restrict__ b1,
    const float* __restrict__ W2, const float* __restrict__ b2,
    const float* __restrict__ x,
    const float* __restrict__ Wg1)
{
    int tid = threadIdx.x;

    if (blockIdx.x < G1_BLOCKS) {
        // ---------- gemm1: h1h = fp16(x @ Wg1) ----------
        __shared__ float4 xs[G1_ROWS * 32];
        int base = blockIdx.x * G1_ROWS;
        const float4* xg = (const float4*)(x + (size_t)base * NF);
        int valid4 = (N_NODES - base) * 32;
#pragma unroll
        for (int i = 0; i < (G1_ROWS * 32) / 256; i++) {
            int idx = tid + i * 256;
            xs[idx] = (idx < valid4) ? xg[idx] : make_float4(0.f, 0.f, 0.f, 0.f);
        }
        __syncthreads();

        int warp = tid >> 5, lane = tid & 31;
        int r0 = warp * 8;
        const float4* Wv = (const float4*)Wg1;

        float4 acc[8];
#pragma unroll
        for (int r = 0; r < 8; r++) acc[r] = make_float4(0.f, 0.f, 0.f, 0.f);

        for (int kt = 0; kt < 32; kt++) {
            float4 w0 = __ldg(&Wv[(kt*4 + 0) * 32 + lane]);
            float4 w1 = __ldg(&Wv[(kt*4 + 1) * 32 + lane]);
            float4 w2 = __ldg(&Wv[(kt*4 + 2) * 32 + lane]);
            float4 w3 = __ldg(&Wv[(kt*4 + 3) * 32 + lane]);
#pragma unroll
            for (int r = 0; r < 8; r++) {
                float4 xv = xs[(r0 + r) * 32 + kt];
                acc[r].x = fmaf(xv.x, w0.x, acc[r].x); acc[r].y = fmaf(xv.x, w0.y, acc[r].y);
                acc[r].z = fmaf(xv.x, w0.z, acc[r].z); acc[r].w = fmaf(xv.x, w0.w, acc[r].w);
                acc[r].x = fmaf(xv.y, w1.x, acc[r].x); acc[r].y = fmaf(xv.y, w1.y, acc[r].y);
                acc[r].z = fmaf(xv.y, w1.z, acc[r].z); acc[r].w = fmaf(xv.y, w1.w, acc[r].w);
                acc[r].x = fmaf(xv.z, w2.x, acc[r].x); acc[r].y = fmaf(xv.z, w2.y, acc[r].y);
                acc[r].z = fmaf(xv.z, w2.z, acc[r].z); acc[r].w = fmaf(xv.z, w2.w, acc[r].w);
                acc[r].x = fmaf(xv.w, w3.x, acc[r].x); acc[r].y = fmaf(xv.w, w3.y, acc[r].y);
                acc[r].z = fmaf(xv.w, w3.z, acc[r].z); acc[r].w = fmaf(xv.w, w3.w, acc[r].w);
            }
        }

#pragma unroll
        for (int r = 0; r < 8; r++) {
            int row = base + r0 + r;
            if (row < N_NODES) {
                uint2 v;
                half2 a = __float22half2_rn(make_float2(acc[r].x, acc[r].y));
                half2 b = __float22half2_rn(make_float2(acc[r].z, acc[r].w));
                v.x = *(unsigned*)&a; v.y = *(unsigned*)&b;
                ((uint2*)(g_h1h + (size_t)row * NF))[lane] = v;
            }
        }
    } else {
        // ---------- edge MLP: weight + bucket fill ----------
        __shared__ float4 sW1[EF * 8];
        __shared__ float4 sb1[8];
        __shared__ float4 sW2[8];
        __shared__ float  sb2;
        for (int i = tid; i < EF * 8; i += 256)
            sW1[i] = ((const float4*)W1)[i];
        if (tid < 8) {
            sb1[tid] = ((const float4*)b1)[tid];
            sW2[tid] = ((const float4*)W2)[tid];
        }
        if (tid == 0) sb2 = b2[0];
        __syncthreads();

        int e = (blockIdx.x - G1_BLOCKS) * 256 + tid;
        if (e >= N_EDGES) return;

        float xv[EF];
        const float4* ex4 = (const float4*)(edge_x + (size_t)e * EF);
#pragma unroll
        for (int q = 0; q < 4; q++) {
            float4 v = ex4[q];
            xv[q*4+0] = v.x; xv[q*4+1] = v.y; xv[q*4+2] = v.z; xv[q*4+3] = v.w;
        }

        float4 h[8];
#pragma unroll
        for (int j = 0; j < 8; j++) h[j] = sb1[j];
#pragma unroll
        for (int k = 0; k < EF; k++) {
            float xk = xv[k];
#pragma unroll
            for (int j = 0; j < 8; j++) {
                float4 w = sW1[k * 8 + j];
                h[j].x = fmaf(xk, w.x, h[j].x);
                h[j].y = fmaf(xk, w.y, h[j].y);
                h[j].z = fmaf(xk, w.z, h[j].z);
                h[j].w = fmaf(xk, w.w, h[j].w);
            }
        }
        float acc = sb2;
#pragma unroll
        for (int j = 0; j < 8; j++) {
            float4 w = sW2[j];
            acc = fmaf(fmaxf(h[j].x, 0.0f), w.x, acc);
            acc = fmaf(fmaxf(h[j].y, 0.0f), w.y, acc);
            acc = fmaf(fmaxf(h[j].z, 0.0f), w.z, acc);
            acc = fmaf(fmaxf(h[j].w, 0.0f), w.w, acc);
        }
        float w = 1.0f / (1.0f + __expf(-acc));

        int r, c;
        if (g_is64) {
            r = eidx[2 * (size_t)e];
            c = eidx[2 * ((size_t)N_EDGES + e)];
        } else {
            r = eidx[e];
            c = eidx[N_EDGES + e];
        }
        r = min(max(r, 0), N_NODES - 1);
        c = min(max(c, 0), N_NODES - 1);

        int pos = atomicAdd(&g_cnt[c], 1);
        if (pos < CAP) g_slot[(size_t)c * CAP + pos] = make_int2(r, __float_as_int(w));
        atomicAdd(&g_deg[c], w);
    }
}

// ---------------- k2: dinv = rsqrt(deg) ----------------
__global__ void k_dinv() {
    int i = blockIdx.x * blockDim.x + threadIdx.x;
    if (i < N_NODES) {
        float d = g_deg[i];
        g_dinv[i] = (d > 0.0f) ? rsqrtf(d) : 0.0f;
    }
}

// ---------------- k4: gather conv1 (warp per node), computes + stores norm ----------------
__global__ __launch_bounds__(256) void k_gather1(const float* __restrict__ bg1) {
    int c    = (blockIdx.x * blockDim.x + threadIdx.x) >> 5;
    int lane = threadIdx.x & 31;
    if (c >= N_NODES) return;

    int   cnt = min(g_cnt[c], CAP);
    float dc  = g_dinv[c];
    float dd  = dc * dc;                 // self-loop weight 1/deg

    float4 acc = __ldg(&((const float4*)bg1)[lane]);
    {
        uint2 v = ((const uint2*)(g_h1h + (size_t)c * NF))[lane];
        float2 a = __half22float2(*(half2*)&v.x);
        float2 b = __half22float2(*(half2*)&v.y);
        acc.x = fmaf(a.x, dd, acc.x); acc.y = fmaf(a.y, dd, acc.y);
        acc.z = fmaf(b.x, dd, acc.z); acc.w = fmaf(b.y, dd, acc.w);
    }

    int2* sl = g_slot + (size_t)c * CAP;
    for (int base = 0; base < cnt; base += 32) {
        int   src = 0;
        float nrm = 0.0f;
        if (base + lane < cnt) {
            int2 p = sl[base + lane];
            src = p.x;
            nrm = g_dinv[p.x] * __int_as_float(p.y) * dc;   // finalize norm
            sl[base + lane].y = __float_as_int(nrm);        // store for conv2
        }
        int m = min(cnt - base, 32);
#pragma unroll 4
        for (int j = 0; j < m; j++) {
            int   s = __shfl_sync(0xFFFFFFFFu, src, j);
            float n = __shfl_sync(0xFFFFFFFFu, nrm, j);
            uint2 v = __ldg(&((const uint2*)(g_h1h + (size_t)s * NF))[lane]);
            float2 a = __half22float2(*(half2*)&v.x);
            float2 b = __half22float2(*(half2*)&v.y);
            acc.x = fmaf(a.x, n, acc.x); acc.y = fmaf(a.y, n, acc.y);
            acc.z = fmaf(b.x, n, acc.z); acc.w = fmaf(b.y, n, acc.w);
        }
    }
    ((float4*)(g_out1 + (size_t)c * NF))[lane] = acc;
}

// ---------------- k5: gemm2: h2h = fp16(relu(out1) @ Wg2) ----------------
#define G2_ROWS 48
__global__ __launch_bounds__(256) void k_gemm2(const float* __restrict__ Wg2) {
    __shared__ float4 xs[G2_ROWS * 32];
    int base = blockIdx.x * G2_ROWS;
    int tid  = threadIdx.x;

    const float4* xg = (const float4*)(g_out1 + (size_t)base * NF);
    int valid4 = (N_NODES - base) * 32;
    for (int i = tid; i < G2_ROWS * 32; i += 256) {
        float4 v = (i < valid4) ? xg[i] : make_float4(0.f, 0.f, 0.f, 0.f);
        v.x = fmaxf(v.x, 0.f); v.y = fmaxf(v.y, 0.f);
        v.z = fmaxf(v.z, 0.f); v.w = fmaxf(v.w, 0.f);
        xs[i] = v;
    }
    __syncthreads();

    if (tid >= 240) return;
    int grp = tid / 40;
    int t   = tid % 40;
    int r0  = grp * 8;

    float acc[8];
#pragma unroll
    for (int r = 0; r < 8; r++) acc[r] = 0.f;

    for (int kt = 0; kt < 32; kt++) {
        float w0 = __ldg(&Wg2[(kt*4 + 0) * CLASSES + t]);
        float w1 = __ldg(&Wg2[(kt*4 + 1) * CLASSES + t]);
        float w2 = __ldg(&Wg2[(kt*4 + 2) * CLASSES + t]);
        float w3 = __ldg(&Wg2[(kt*4 + 3) * CLASSES + t]);
#pragma unroll
        for (int r = 0; r < 8; r++) {
            float4 xv = xs[(r0 + r) * 32 + kt];
            acc[r] = fmaf(xv.x, w0, acc[r]);
            acc[r] = fmaf(xv.y, w1, acc[r]);
            acc[r] = fmaf(xv.z, w2, acc[r]);
            acc[r] = fmaf(xv.w, w3, acc[r]);
        }
    }

#pragma unroll
    for (int r = 0; r < 8; r++) {
        int row = base + r0 + r;
        if (row < N_NODES)
            g_h2h[(size_t)row * CLASSES + t] = __float2half_rn(acc[r]);
    }
}

// ---------------- k6: gather conv2 (warp per node, 40 fp16 feats) ----------------
__global__ __launch_bounds__(256) void k_gather2(
    const float* __restrict__ bg2, float* __restrict__ out2)
{
    int c    = (blockIdx.x * blockDim.x + threadIdx.x) >> 5;
    int lane = threadIdx.x & 31;
    if (c >= N_NODES) return;

    int   cnt = min(g_cnt[c], CAP);
    float dc  = g_dinv[c];
    float dd  = dc * dc;

    float acc0 = __ldg(&bg2[lane]);
    float acc1 = (lane < 8) ? __ldg(&bg2[32 + lane]) : 0.f;
    {
        const __half* hc = g_h2h + (size_t)c * CLASSES;
        acc0 = fmaf(__half2float(hc[lane]), dd, acc0);
        if (lane < 8) acc1 = fmaf(__half2float(hc[32 + lane]), dd, acc1);
    }

    const int2* sl = g_slot + (size_t)c * CAP;
    for (int base = 0; base < cnt; base += 32) {
        int   src = 0;
        float nrm = 0.0f;
        if (base + lane < cnt) {
            int2 p = sl[base + lane];
            src = p.x;
            nrm = __int_as_float(p.y);
        }
        int m = min(cnt - base, 32);
#pragma unroll 4
        for (int j = 0; j < m; j++) {
            int   s = __shfl_sync(0xFFFFFFFFu, src, j);
            float n = __shfl_sync(0xFFFFFFFFu, nrm, j);
            const __half* hs = g_h2h + (size_t)s * CLASSES;
            acc0 = fmaf(__half2float(__ldg(&hs[lane])), n, acc0);
            if (lane < 8) acc1 = fmaf(__half2float(__ldg(&hs[32 + lane])), n, acc1);
        }
    }
    out2[(size_t)c * CLASSES + lane] = acc0;
    if (lane < 8) out2[(size_t)c * CLASSES + 32 + lane] = acc1;
}

// ---------------- launch ----------------
extern "C" void kernel_launch(void* const* d_in, const int* in_sizes, int n_in,
                              void* d_out, int out_size)
{
    const float* x      = (const float*)d_in[0];
    const int*   eidx   = (const int*)d_in[1];
    const float* edge_x = (const float*)d_in[2];
    const float* W1     = (const float*)d_in[3];
    const float* b1     = (const float*)d_in[4];
    const float* W2     = (const float*)d_in[5];
    const float* b2     = (const float*)d_in[6];
    const float* Wg1    = (const float*)d_in[7];
    const float* bg1    = (const float*)d_in[8];
    const float* Wg2    = (const float*)d_in[9];
    const float* bg2    = (const float*)d_in[10];
    float*       out2   = (float*)d_out;

    k_init_detect<<<(N_NODES + 255) / 256, 256>>>(eidx);
    k_mlp_gemm1<<<G1_BLOCKS + MLP_BLOCKS, 256>>>(edge_x, eidx, W1, b1, W2, b2, x, Wg1);
    k_dinv<<<(N_NODES + 255) / 256, 256>>>();
    k_gather1<<<(N_NODES * 32 + 255) / 256, 256>>>(bg1);
    k_gemm2<<<(N_NODES + G2_ROWS - 1) / G2_ROWS, 256>>>(Wg2);
    k_gather2<<<(N_NODES * 32 + 255) / 256, 256>>>(bg2, out2);
}

// round 6
// speedup vs baseline: 4.0260x; 1.0665x over previous
#include <cuda_runtime.h>
#include <cuda_fp16.h>
#include <math.h>

#define N_NODES 50000
#define N_EDGES 1600000
#define NF      128
#define EF      16
#define EFIL    32
#define CLASSES 40
#define CAP     128   // per-node in-edge bucket capacity (Poisson(32); P(>128) ~ 1e-35)

// ---------------- device scratch (no allocations allowed) ----------------
__device__ int    g_is64;
__device__ float  g_deg [N_NODES];
__device__ float  g_dinv[N_NODES];
__device__ int    g_cnt [N_NODES];
__device__ int2   g_slot[(size_t)N_NODES * CAP];  // (src, w-bits) -> (src, norm-bits)
__device__ __half g_h1h [(size_t)N_NODES * NF];   // fp16 messages, layer 1
__device__ float  g_out1[(size_t)N_NODES * NF];
__device__ __half g_h2h [(size_t)N_NODES * CLASSES];

// ---------------- k0: deg=1, cnt=0, + int32/int64 detect (block 0) ----------------
__global__ void k_init_detect(const int* __restrict__ w) {
    int i = blockIdx.x * blockDim.x + threadIdx.x;
    if (i < N_NODES) { g_deg[i] = 1.0f; g_cnt[i] = 0; }
    if (blockIdx.x == 0) {
        __shared__ int any_nonzero;
        if (threadIdx.x == 0) any_nonzero = 0;
        __syncthreads();
        if (w[2 * threadIdx.x + 1] != 0) atomicOr(&any_nonzero, 1);
        __syncthreads();
        if (threadIdx.x == 0) g_is64 = (any_nonzero == 0) ? 1 : 0;
    }
}

// ---------------- k1: fused [gemm1 | edge MLP] by block range ----------------
#define G1_ROWS   64
#define G1_BLOCKS ((N_NODES + G1_ROWS - 1) / G1_ROWS)          // 782
#define MLP_BLOCKS ((N_EDGES + 255) / 256)                     // 6250

__global__ __launch_bounds__(256) void k_mlp_gemm1(
    const float* __restrict__ edge_x,
    const int*   __restrict__ eidx,
    const float* __restrict__ W1, const float* __restrict__ b1,
    const float* __restrict__ W2, const float* __restrict__ b2,
    const float* __restrict__ x,
    const float* __restrict__ Wg1)
{
    int tid = threadIdx.x;

    if (blockIdx.x < G1_BLOCKS) {
        // ---------- gemm1: h1h = fp16(x @ Wg1) ----------
        __shared__ float4 xs[G1_ROWS * 32];
        int base = blockIdx.x * G1_ROWS;
        const float4* xg = (const float4*)(x + (size_t)base * NF);
        int valid4 = (N_NODES - base) * 32;
#pragma unroll
        for (int i = 0; i < (G1_ROWS * 32) / 256; i++) {
            int idx = tid + i * 256;
            xs[idx] = (idx < valid4) ? xg[idx] : make_float4(0.f, 0.f, 0.f, 0.f);
        }
        __syncthreads();

        int warp = tid >> 5, lane = tid & 31;
        int r0 = warp * 8;
        const float4* Wv = (const float4*)Wg1;

        float4 acc[8];
#pragma unroll
        for (int r = 0; r < 8; r++) acc[r] = make_float4(0.f, 0.f, 0.f, 0.f);

        for (int kt = 0; kt < 32; kt++) {
            float4 w0 = __ldg(&Wv[(kt*4 + 0) * 32 + lane]);
            float4 w1 = __ldg(&Wv[(kt*4 + 1) * 32 + lane]);
            float4 w2 = __ldg(&Wv[(kt*4 + 2) * 32 + lane]);
            float4 w3 = __ldg(&Wv[(kt*4 + 3) * 32 + lane]);
#pragma unroll
            for (int r = 0; r < 8; r++) {
                float4 xv = xs[(r0 + r) * 32 + kt];
                acc[r].x = fmaf(xv.x, w0.x, acc[r].x); acc[r].y = fmaf(xv.x, w0.y, acc[r].y);
                acc[r].z = fmaf(xv.x, w0.z, acc[r].z); acc[r].w = fmaf(xv.x, w0.w, acc[r].w);
                acc[r].x = fmaf(xv.y, w1.x, acc[r].x); acc[r].y = fmaf(xv.y, w1.y, acc[r].y);
                acc[r].z = fmaf(xv.y, w1.z, acc[r].z); acc[r].w = fmaf(xv.y, w1.w, acc[r].w);
                acc[r].x = fmaf(xv.z, w2.x, acc[r].x); acc[r].y = fmaf(xv.z, w2.y, acc[r].y);
                acc[r].z = fmaf(xv.z, w2.z, acc[r].z); acc[r].w = fmaf(xv.z, w2.w, acc[r].w);
                acc[r].x = fmaf(xv.w, w3.x, acc[r].x); acc[r].y = fmaf(xv.w, w3.y, acc[r].y);
                acc[r].z = fmaf(xv.w, w3.z, acc[r].z); acc[r].w = fmaf(xv.w, w3.w, acc[r].w);
            }
        }

#pragma unroll
        for (int r = 0; r < 8; r++) {
            int row = base + r0 + r;
            if (row < N_NODES) {
                uint2 v;
                half2 a = __float22half2_rn(make_float2(acc[r].x, acc[r].y));
                half2 b = __float22half2_rn(make_float2(acc[r].z, acc[r].w));
                v.x = *(unsigned*)&a; v.y = *(unsigned*)&b;
                ((uint2*)(g_h1h + (size_t)row * NF))[lane] = v;
            }
        }
    } else {
        // ---------- edge MLP: weight + bucket fill ----------
        __shared__ float4 sW1[EF * 8];
        __shared__ float4 sb1[8];
        __shared__ float4 sW2[8];
        __shared__ float  sb2;
        for (int i = tid; i < EF * 8; i += 256)
            sW1[i] = ((const float4*)W1)[i];
        if (tid < 8) {
            sb1[tid] = ((const float4*)b1)[tid];
            sW2[tid] = ((const float4*)W2)[tid];
        }
        if (tid == 0) sb2 = b2[0];
        __syncthreads();

        int e = (blockIdx.x - G1_BLOCKS) * 256 + tid;
        if (e >= N_EDGES) return;

        float xv[EF];
        const float4* ex4 = (const float4*)(edge_x + (size_t)e * EF);
#pragma unroll
        for (int q = 0; q < 4; q++) {
            float4 v = ex4[q];
            xv[q*4+0] = v.x; xv[q*4+1] = v.y; xv[q*4+2] = v.z; xv[q*4+3] = v.w;
        }

        float4 h[8];
#pragma unroll
        for (int j = 0; j < 8; j++) h[j] = sb1[j];
#pragma unroll
        for (int k = 0; k < EF; k++) {
            float xk = xv[k];
#pragma unroll
            for (int j = 0; j < 8; j++) {
                float4 w = sW1[k * 8 + j];
                h[j].x = fmaf(xk, w.x, h[j].x);
                h[j].y = fmaf(xk, w.y, h[j].y);
                h[j].z = fmaf(xk, w.z, h[j].z);
                h[j].w = fmaf(xk, w.w, h[j].w);
            }
        }
        float acc = sb2;
#pragma unroll
        for (int j = 0; j < 8; j++) {
            float4 w = sW2[j];
            acc = fmaf(fmaxf(h[j].x, 0.0f), w.x, acc);
            acc = fmaf(fmaxf(h[j].y, 0.0f), w.y, acc);
            acc = fmaf(fmaxf(h[j].z, 0.0f), w.z, acc);
            acc = fmaf(fmaxf(h[j].w, 0.0f), w.w, acc);
        }
        float w = 1.0f / (1.0f + __expf(-acc));

        int r, c;
        if (g_is64) {
            r = eidx[2 * (size_t)e];
            c = eidx[2 * ((size_t)N_EDGES + e)];
        } else {
            r = eidx[e];
            c = eidx[N_EDGES + e];
        }
        r = min(max(r, 0), N_NODES - 1);
        c = min(max(c, 0), N_NODES - 1);

        int pos = atomicAdd(&g_cnt[c], 1);
        if (pos < CAP) g_slot[(size_t)c * CAP + pos] = make_int2(r, __float_as_int(w));
        atomicAdd(&g_deg[c], w);
    }
}

// ---------------- k2: dinv = rsqrt(deg) ----------------
__global__ void k_dinv() {
    int i = blockIdx.x * blockDim.x + threadIdx.x;
    if (i < N_NODES) {
        float d = g_deg[i];
        g_dinv[i] = (d > 0.0f) ? rsqrtf(d) : 0.0f;
    }
}

// ---------------- k4: gather conv1 — warp/node, 2 slots in flight, LDG.128 ----------------
__global__ __launch_bounds__(256) void k_gather1(const float* __restrict__ bg1) {
    int c    = (blockIdx.x * blockDim.x + threadIdx.x) >> 5;
    int lane = threadIdx.x & 31;
    if (c >= N_NODES) return;

    int   cnt = min(g_cnt[c], CAP);
    float dc  = g_dinv[c];
    float dd  = dc * dc;                 // self-loop weight 1/deg

    int half = lane >> 4;                // 0: even slots, 1: odd slots
    int hl   = lane & 15;                // 16 lanes x uint4 = 256B row

    float acc[8];
#pragma unroll
    for (int k = 0; k < 8; k++) acc[k] = 0.f;

    int2* sl = g_slot + (size_t)c * CAP;
    for (int base = 0; base < cnt; base += 32) {
        int   src = 0;
        float nrm = 0.0f;
        if (base + lane < cnt) {
            int2 p = sl[base + lane];
            src = p.x;
            nrm = g_dinv[p.x] * __int_as_float(p.y) * dc;   // finalize norm
            sl[base + lane].y = __float_as_int(nrm);        // store for conv2
        }
        int m = min(cnt - base, 32);
        for (int j = 0; j < m; j += 2) {
            int jj = j + half;
            int   s = __shfl_sync(0xFFFFFFFFu, src, jj & 31);
            float n = __shfl_sync(0xFFFFFFFFu, nrm, jj & 31);
            if (jj < m) {
                uint4 v = __ldg(&((const uint4*)(g_h1h + (size_t)s * NF))[hl]);
                half2* hp = (half2*)&v;
#pragma unroll
                for (int k = 0; k < 4; k++) {
                    float2 f = __half22float2(hp[k]);
                    acc[2*k]   = fmaf(f.x, n, acc[2*k]);
                    acc[2*k+1] = fmaf(f.y, n, acc[2*k+1]);
                }
            }
        }
    }
    // combine the two slot-halves (same features in lanes l and l+16)
#pragma unroll
    for (int k = 0; k < 8; k++)
        acc[k] += __shfl_xor_sync(0xFFFFFFFFu, acc[k], 16);

    if (half == 0) {
        // self-loop + bias, then write 8 floats
        uint4 v = ((const uint4*)(g_h1h + (size_t)c * NF))[hl];
        half2* hp = (half2*)&v;
        const float4* bv = (const float4*)(bg1 + hl * 8);
        float4 b0 = __ldg(&bv[0]);
        float4 b1 = __ldg(&bv[1]);
        float bb[8] = {b0.x, b0.y, b0.z, b0.w, b1.x, b1.y, b1.z, b1.w};
#pragma unroll
        for (int k = 0; k < 4; k++) {
            float2 f = __half22float2(hp[k]);
            acc[2*k]   = fmaf(f.x, dd, acc[2*k])   + bb[2*k];
            acc[2*k+1] = fmaf(f.y, dd, acc[2*k+1]) + bb[2*k+1];
        }
        float4* out = (float4*)(g_out1 + (size_t)c * NF + hl * 8);
        out[0] = make_float4(acc[0], acc[1], acc[2], acc[3]);
        out[1] = make_float4(acc[4], acc[5], acc[6], acc[7]);
    }
}

// ---------------- k5: gemm2: h2h = fp16(relu(out1) @ Wg2) ----------------
#define G2_ROWS 48
__global__ __launch_bounds__(256) void k_gemm2(const float* __restrict__ Wg2) {
    __shared__ float4 xs[G2_ROWS * 32];
    int base = blockIdx.x * G2_ROWS;
    int tid  = threadIdx.x;

    const float4* xg = (const float4*)(g_out1 + (size_t)base * NF);
    int valid4 = (N_NODES - base) * 32;
    for (int i = tid; i < G2_ROWS * 32; i += 256) {
        float4 v = (i < valid4) ? xg[i] : make_float4(0.f, 0.f, 0.f, 0.f);
        v.x = fmaxf(v.x, 0.f); v.y = fmaxf(v.y, 0.f);
        v.z = fmaxf(v.z, 0.f); v.w = fmaxf(v.w, 0.f);
        xs[i] = v;
    }
    __syncthreads();

    if (tid >= 240) return;
    int grp = tid / 40;
    int t   = tid % 40;
    int r0  = grp * 8;

    float acc[8];
#pragma unroll
    for (int r = 0; r < 8; r++) acc[r] = 0.f;

    for (int kt = 0; kt < 32; kt++) {
        float w0 = __ldg(&Wg2[(kt*4 + 0) * CLASSES + t]);
        float w1 = __ldg(&Wg2[(kt*4 + 1) * CLASSES + t]);
        float w2 = __ldg(&Wg2[(kt*4 + 2) * CLASSES + t]);
        float w3 = __ldg(&Wg2[(kt*4 + 3) * CLASSES + t]);
#pragma unroll
        for (int r = 0; r < 8; r++) {
            float4 xv = xs[(r0 + r) * 32 + kt];
            acc[r] = fmaf(xv.x, w0, acc[r]);
            acc[r] = fmaf(xv.y, w1, acc[r]);
            acc[r] = fmaf(xv.z, w2, acc[r]);
            acc[r] = fmaf(xv.w, w3, acc[r]);
        }
    }

#pragma unroll
    for (int r = 0; r < 8; r++) {
        int row = base + r0 + r;
        if (row < N_NODES)
            g_h2h[(size_t)row * CLASSES + t] = __float2half_rn(acc[r]);
    }
}

// ---------------- k6: gather conv2 — warp/node, 3 slots in flight, LDG.64 ----------------
__global__ __launch_bounds__(256) void k_gather2(
    const float* __restrict__ bg2, float* __restrict__ out2)
{
    int c    = (blockIdx.x * blockDim.x + threadIdx.x) >> 5;
    int lane = threadIdx.x & 31;
    if (c >= N_NODES) return;

    int   cnt = min(g_cnt[c], CAP);
    float dc  = g_dinv[c];
    float dd  = dc * dc;

    int sub = lane / 10;                 // 0,1,2 active; 3 (lanes 30,31) idle
    int q   = lane - sub * 10;           // 10 lanes x uint2 (4 halves) = 80B row
    bool act = (lane < 30);

    float acc[4] = {0.f, 0.f, 0.f, 0.f};

    const int2* sl = g_slot + (size_t)c * CAP;
    for (int base = 0; base < cnt; base += 32) {
        int   src = 0;
        float nrm = 0.0f;
        if (base + lane < cnt) {
            int2 p = sl[base + lane];
            src = p.x;
            nrm = __int_as_float(p.y);   // finalized in gather1
        }
        int m = min(cnt - base, 32);
        for (int j = 0; j < m; j += 3) {
            int jj = j + sub;
            int   s = __shfl_sync(0xFFFFFFFFu, src, jj & 31);
            float n = __shfl_sync(0xFFFFFFFFu, nrm, jj & 31);
            if (act && jj < m) {
                uint2 v = __ldg((const uint2*)(g_h2h + (size_t)s * CLASSES) + q);
                half2* hp = (half2*)&v;
                float2 f0 = __half22float2(hp[0]);
                float2 f1 = __half22float2(hp[1]);
                acc[0] = fmaf(f0.x, n, acc[0]);
                acc[1] = fmaf(f0.y, n, acc[1]);
                acc[2] = fmaf(f1.x, n, acc[2]);
                acc[3] = fmaf(f1.y, n, acc[3]);
            }
        }
    }
    // reduce the 3 sub-slot accumulators into lanes 0-9
#pragma unroll
    for (int k = 0; k < 4; k++) {
        float v1 = __shfl_down_sync(0xFFFFFFFFu, acc[k], 10);
        float v2 = __shfl_down_sync(0xFFFFFFFFu, acc[k], 20);
        acc[k] += v1 + v2;
    }

    if (lane < 10) {
        uint2 v = ((const uint2*)(g_h2h + (size_t)c * CLASSES))[lane];
        half2* hp = (half2*)&v;
        float2 f0 = __half22float2(hp[0]);
        float2 f1 = __half22float2(hp[1]);
        float4 b = __ldg(&((const float4*)bg2)[lane]);
        float4 o;
        o.x = fmaf(f0.x, dd, acc[0]) + b.x;
        o.y = fmaf(f0.y, dd, acc[1]) + b.y;
        o.z = fmaf(f1.x, dd, acc[2]) + b.z;
        o.w = fmaf(f1.y, dd, acc[3]) + b.w;
        ((float4*)(out2 + (size_t)c * CLASSES))[lane] = o;
    }
}

// ---------------- launch ----------------
extern "C" void kernel_launch(void* const* d_in, const int* in_sizes, int n_in,
                              void* d_out, int out_size)
{
    const float* x      = (const float*)d_in[0];
    const int*   eidx   = (const int*)d_in[1];
    const float* edge_x = (const float*)d_in[2];
    const float* W1     = (const float*)d_in[3];
    const float* b1     = (const float*)d_in[4];
    const float* W2     = (const float*)d_in[5];
    const float* b2     = (const float*)d_in[6];
    const float* Wg1    = (const float*)d_in[7];
    const float* bg1    = (const float*)d_in[8];
    const float* Wg2    = (const float*)d_in[9];
    const float* bg2    = (const float*)d_in[10];
    float*       out2   = (float*)d_out;

    k_init_detect<<<(N_NODES + 255) / 256, 256>>>(eidx);
    k_mlp_gemm1<<<G1_BLOCKS + MLP_BLOCKS, 256>>>(edge_x, eidx, W1, b1, W2, b2, x, Wg1);
    k_dinv<<<(N_NODES + 255) / 256, 256>>>();
    k_gather1<<<(N_NODES * 32 + 255) / 256, 256>>>(bg1);
    k_gemm2<<<(N_NODES + G2_ROWS - 1) / G2_ROWS, 256>>>(Wg2);
    k_gather2<<<(N_NODES * 32 + 255) / 256, 256>>>(bg2, out2);
}

// round 8
// speedup vs baseline: 4.3599x; 1.0829x over previous
#include <cuda_runtime.h>
#include <cuda_fp16.h>
#include <mma.h>
#include <math.h>

using namespace nvcuda;

#define N_NODES 50000
#define N_EDGES 1600000
#define NF      128
#define EF      16
#define EFIL    32
#define CLASSES 40
#define CAP     128   // per-node bucket capacity (Poisson(32); P(>128) ~ 1e-35)
#define N2PAD   64    // padded Wg2 column count for wmma

// ---------------- device scratch (no allocations allowed) ----------------
__device__ int    g_is64;
__device__ float  g_deg [N_NODES];
__device__ float  g_dinv[N_NODES];
__device__ int    g_cnt [N_NODES];
__device__ int2   g_slot[(size_t)N_NODES * CAP];
__device__ __align__(16) __half g_wg1h[NF * NF];          // fp16 Wg1
__device__ __align__(16) __half g_wg2h[NF * N2PAD];       // fp16 Wg2, zero-padded
__device__ __align__(16) __half g_h1h [(size_t)N_NODES * NF];       // fp16 x@Wg1
__device__ __align__(16) __half g_r1h [(size_t)N_NODES * NF];       // fp16 relu(out1)
__device__ __align__(16) __half g_h2h [(size_t)N_NODES * CLASSES];  // fp16 relu(out1)@Wg2

// ---------------- k0: deg=1, cnt=0, weight fp16 conversion, dtype detect ----------------
__global__ void k_init_detect(const int* __restrict__ w,
                              const float* __restrict__ Wg1,
                              const float* __restrict__ Wg2) {
    int i = blockIdx.x * blockDim.x + threadIdx.x;
    if (i < N_NODES) { g_deg[i] = 1.0f; g_cnt[i] = 0; }
    if (i < NF * NF) g_wg1h[i] = __float2half(Wg1[i]);
    if (i < NF * N2PAD) {
        int k = i / N2PAD, n = i % N2PAD;
        g_wg2h[i] = (n < CLASSES) ? __float2half(Wg2[k * CLASSES + n]) : __half(0.0f);
    }
    if (blockIdx.x == 0) {
        __shared__ int any_nonzero;
        if (threadIdx.x == 0) any_nonzero = 0;
        __syncthreads();
        if (w[2 * threadIdx.x + 1] != 0) atomicOr(&any_nonzero, 1);
        __syncthreads();
        if (threadIdx.x == 0) g_is64 = (any_nonzero == 0) ? 1 : 0;
    }
}

// ---------------- k1: fused [tensor gemm1 | edge MLP] by block range ----------------
#define G1_ROWS   64
#define G1_BLOCKS ((N_NODES + G1_ROWS - 1) / G1_ROWS)          // 782
#define MLP_BLOCKS ((N_EDGES + 255) / 256)                     // 6250

__global__ __launch_bounds__(256) void k_mlp_gemm1(
    const float* __restrict__ edge_x,
    const int*   __restrict__ eidx,
    const float* __restrict__ W1, const float* __restrict__ b1,
    const float* __restrict__ W2, const float* __restrict__ b2,
    const float* __restrict__ x)
{
    __shared__ __align__(16) char sbuf[32768];
    int tid = threadIdx.x;

    if (blockIdx.x < G1_BLOCKS) {
        // ---------- gemm1: h1h = fp16(x @ Wg1), tensor cores ----------
        __half* a  = (__half*)sbuf;          // phase 1-2: 64x128 fp16 (16KB)
        float*  ob = (float*)sbuf;           // phase 3:   64x128 fp32 (32KB)
        int base = blockIdx.x * G1_ROWS;
        const float4* xg = (const float4*)(x + (size_t)base * NF);
        int valid4 = (N_NODES - base) * 32;
#pragma unroll
        for (int i = 0; i < (G1_ROWS * 32) / 256; i++) {
            int idx = tid + i * 256;
            float4 v = (idx < valid4) ? xg[idx] : make_float4(0.f, 0.f, 0.f, 0.f);
            half2 p0 = __float22half2_rn(make_float2(v.x, v.y));
            half2 p1 = __float22half2_rn(make_float2(v.z, v.w));
            uint2 u; u.x = *(unsigned*)&p0; u.y = *(unsigned*)&p1;
            ((uint2*)a)[idx] = u;
        }
        __syncthreads();

        int wid = tid >> 5;
        int rt  = wid & 3;          // row tile 0..3
        int nh  = wid >> 2;         // col half 0..1

        wmma::fragment<wmma::matrix_a, 16, 16, 16, half, wmma::row_major> fa;
        wmma::fragment<wmma::matrix_b, 16, 16, 16, half, wmma::row_major> fb;
        wmma::fragment<wmma::accumulator, 16, 16, 16, float> fc[4];
#pragma unroll
        for (int n = 0; n < 4; n++) wmma::fill_fragment(fc[n], 0.0f);

        for (int k8 = 0; k8 < 8; k8++) {
            wmma::load_matrix_sync(fa, a + rt * 16 * NF + k8 * 16, NF);
#pragma unroll
            for (int n = 0; n < 4; n++) {
                wmma::load_matrix_sync(fb, g_wg1h + k8 * 16 * NF + nh * 64 + n * 16, NF);
                wmma::mma_sync(fc[n], fa, fb, fc[n]);
            }
        }
        __syncthreads();   // everyone done reading a before overwrite
#pragma unroll
        for (int n = 0; n < 4; n++)
            wmma::store_matrix_sync(ob + rt * 16 * NF + nh * 64 + n * 16, fc[n], NF, wmma::mem_row_major);
        __syncthreads();

        // convert to fp16 and write
        for (int idx = tid; idx < G1_ROWS * 64; idx += 256) {  // half2 units
            int row = idx >> 6;
            int c2  = idx & 63;
            int gr = base + row;
            if (gr < N_NODES) {
                float2 f = ((const float2*)ob)[idx];
                half2 h = __float22half2_rn(f);
                *(half2*)(g_h1h + (size_t)gr * NF + c2 * 2) = h;
            }
        }
    } else {
        // ---------- edge MLP: weight + bucket fill ----------
        float4* sW1 = (float4*)sbuf;                    // EF*8 float4
        float4* sb1 = sW1 + EF * 8;
        float4* sW2 = sb1 + 8;
        float*  sb2 = (float*)(sW2 + 8);
        for (int i = tid; i < EF * 8; i += 256)
            sW1[i] = ((const float4*)W1)[i];
        if (tid < 8) {
            sb1[tid] = ((const float4*)b1)[tid];
            sW2[tid] = ((const float4*)W2)[tid];
        }
        if (tid == 0) *sb2 = b2[0];
        __syncthreads();

        int e = (blockIdx.x - G1_BLOCKS) * 256 + tid;
        if (e >= N_EDGES) return;

        float xv[EF];
        const float4* ex4 = (const float4*)(edge_x + (size_t)e * EF);
#pragma unroll
        for (int q = 0; q < 4; q++) {
            float4 v = ex4[q];
            xv[q*4+0] = v.x; xv[q*4+1] = v.y; xv[q*4+2] = v.z; xv[q*4+3] = v.w;
        }

        float4 h[8];
#pragma unroll
        for (int j = 0; j < 8; j++) h[j] = sb1[j];
#pragma unroll
        for (int k = 0; k < EF; k++) {
            float xk = xv[k];
#pragma unroll
            for (int j = 0; j < 8; j++) {
                float4 w = sW1[k * 8 + j];
                h[j].x = fmaf(xk, w.x, h[j].x);
                h[j].y = fmaf(xk, w.y, h[j].y);
                h[j].z = fmaf(xk, w.z, h[j].z);
                h[j].w = fmaf(xk, w.w, h[j].w);
            }
        }
        float acc = *sb2;
#pragma unroll
        for (int j = 0; j < 8; j++) {
            float4 w = sW2[j];
            acc = fmaf(fmaxf(h[j].x, 0.0f), w.x, acc);
            acc = fmaf(fmaxf(h[j].y, 0.0f), w.y, acc);
            acc = fmaf(fmaxf(h[j].z, 0.0f), w.z, acc);
            acc = fmaf(fmaxf(h[j].w, 0.0f), w.w, acc);
        }
        float w = 1.0f / (1.0f + __expf(-acc));

        int r, c;
        if (g_is64) {
            r = eidx[2 * (size_t)e];
            c = eidx[2 * ((size_t)N_EDGES + e)];
        } else {
            r = eidx[e];
            c = eidx[N_EDGES + e];
        }
        r = min(max(r, 0), N_NODES - 1);
        c = min(max(c, 0), N_NODES - 1);

        int pos = atomicAdd(&g_cnt[c], 1);
        if (pos < CAP) g_slot[(size_t)c * CAP + pos] = make_int2(r, __float_as_int(w));
        atomicAdd(&g_deg[c], w);
    }
}

// ---------------- k2: dinv = rsqrt(deg) ----------------
__global__ void k_dinv() {
    int i = blockIdx.x * blockDim.x + threadIdx.x;
    if (i < N_NODES) {
        float d = g_deg[i];
        g_dinv[i] = (d > 0.0f) ? rsqrtf(d) : 0.0f;
    }
}

// ---------------- k4: gather conv1 — warp/node, 2 slots in flight; writes relu fp16 ----------------
__global__ __launch_bounds__(256) void k_gather1(const float* __restrict__ bg1) {
    int c    = (blockIdx.x * blockDim.x + threadIdx.x) >> 5;
    int lane = threadIdx.x & 31;
    if (c >= N_NODES) return;

    int   cnt = min(g_cnt[c], CAP);
    float dc  = g_dinv[c];
    float dd  = dc * dc;

    int half_ = lane >> 4;
    int hl    = lane & 15;

    float acc[8];
#pragma unroll
    for (int k = 0; k < 8; k++) acc[k] = 0.f;

    int2* sl = g_slot + (size_t)c * CAP;
    for (int base = 0; base < cnt; base += 32) {
        int   src = 0;
        float nrm = 0.0f;
        if (base + lane < cnt) {
            int2 p = sl[base + lane];
            src = p.x;
            nrm = g_dinv[p.x] * __int_as_float(p.y) * dc;
            sl[base + lane].y = __float_as_int(nrm);
        }
        int m = min(cnt - base, 32);
        for (int j = 0; j < m; j += 2) {
            int jj = j + half_;
            int   s = __shfl_sync(0xFFFFFFFFu, src, jj & 31);
            float n = __shfl_sync(0xFFFFFFFFu, nrm, jj & 31);
            if (jj < m) {
                uint4 v = __ldg(&((const uint4*)(g_h1h + (size_t)s * NF))[hl]);
                half2* hp = (half2*)&v;
#pragma unroll
                for (int k = 0; k < 4; k++) {
                    float2 f = __half22float2(hp[k]);
                    acc[2*k]   = fmaf(f.x, n, acc[2*k]);
                    acc[2*k+1] = fmaf(f.y, n, acc[2*k+1]);
                }
            }
        }
    }
#pragma unroll
    for (int k = 0; k < 8; k++)
        acc[k] += __shfl_xor_sync(0xFFFFFFFFu, acc[k], 16);

    if (half_ == 0) {
        uint4 v = ((const uint4*)(g_h1h + (size_t)c * NF))[hl];
        half2* hp = (half2*)&v;
        const float4* bv = (const float4*)(bg1 + hl * 8);
        float4 b0 = __ldg(&bv[0]);
        float4 b1 = __ldg(&bv[1]);
        float bb[8] = {b0.x, b0.y, b0.z, b0.w, b1.x, b1.y, b1.z, b1.w};
        half2 o[4];
#pragma unroll
        for (int k = 0; k < 4; k++) {
            float2 f = __half22float2(hp[k]);
            float v0 = fmaxf(fmaf(f.x, dd, acc[2*k])   + bb[2*k],   0.0f);
            float v1 = fmaxf(fmaf(f.y, dd, acc[2*k+1]) + bb[2*k+1], 0.0f);
            o[k] = __float22half2_rn(make_float2(v0, v1));
        }
        uint4 u;
        u.x = *(unsigned*)&o[0]; u.y = *(unsigned*)&o[1];
        u.z = *(unsigned*)&o[2]; u.w = *(unsigned*)&o[3];
        ((uint4*)(g_r1h + (size_t)c * NF))[hl] = u;
    }
}

// ---------------- k5: gemm2 tensor: h2h = fp16(r1h @ Wg2h) ----------------
// 64 rows x 48 cols (of 64-padded), 192 threads = 6 warps, warp = 2 of 12 tiles
__global__ __launch_bounds__(192) void k_gemm2() {
    __shared__ __align__(16) __half a2[G1_ROWS * NF];     // 16KB
    __shared__ __align__(16) float  ob[G1_ROWS * 48];     // 12KB
    int base = blockIdx.x * G1_ROWS;
    int tid  = threadIdx.x;

    const uint4* rg = (const uint4*)(g_r1h + (size_t)base * NF);
    int valid8 = (N_NODES - base) * 16;                   // uint4 = 8 halves
    for (int i = tid; i < G1_ROWS * 16; i += 192) {
        uint4 v = (i < valid8) ? rg[i] : make_uint4(0, 0, 0, 0);
        ((uint4*)a2)[i] = v;
    }
    __syncthreads();

    int wid = tid >> 5;            // 0..5
    wmma::fragment<wmma::matrix_a, 16, 16, 16, half, wmma::row_major> fa;
    wmma::fragment<wmma::matrix_b, 16, 16, 16, half, wmma::row_major> fb;
    wmma::fragment<wmma::accumulator, 16, 16, 16, float> fc;

#pragma unroll
    for (int i = 0; i < 2; i++) {
        int t  = wid * 2 + i;      // 0..11
        int rt = t / 3, ct = t % 3;
        wmma::fill_fragment(fc, 0.0f);
        for (int k8 = 0; k8 < 8; k8++) {
            wmma::load_matrix_sync(fa, a2 + rt * 16 * NF + k8 * 16, NF);
            wmma::load_matrix_sync(fb, g_wg2h + k8 * 16 * N2PAD + ct * 16, N2PAD);
            wmma::mma_sync(fc, fa, fb, fc);
        }
        wmma::store_matrix_sync(ob + rt * 16 * 48 + ct * 16, fc, 48, wmma::mem_row_major);
    }
    __syncthreads();

    // write 64 x 40 fp16 (drop pad cols)
    for (int idx = tid; idx < G1_ROWS * 20; idx += 192) {  // half2 units
        int row = idx / 20;
        int c2  = idx % 20;
        int gr  = base + row;
        if (gr < N_NODES) {
            float2 f = make_float2(ob[row * 48 + c2 * 2], ob[row * 48 + c2 * 2 + 1]);
            *(half2*)(g_h2h + (size_t)gr * CLASSES + c2 * 2) = __float22half2_rn(f);
        }
    }
}

// ---------------- k6: gather conv2 — warp/node, 3 slots in flight ----------------
__global__ __launch_bounds__(256) void k_gather2(
    const float* __restrict__ bg2, float* __restrict__ out2)
{
    int c    = (blockIdx.x * blockDim.x + threadIdx.x) >> 5;
    int lane = threadIdx.x & 31;
    if (c >= N_NODES) return;

    int   cnt = min(g_cnt[c], CAP);
    float dc  = g_dinv[c];
    float dd  = dc * dc;

    int sub = lane / 10;
    int q   = lane - sub * 10;
    bool act = (lane < 30);

    float acc[4] = {0.f, 0.f, 0.f, 0.f};

    const int2* sl = g_slot + (size_t)c * CAP;
    for (int base = 0; base < cnt; base += 32) {
        int   src = 0;
        float nrm = 0.0f;
        if (base + lane < cnt) {
            int2 p = sl[base + lane];
            src = p.x;
            nrm = __int_as_float(p.y);
        }
        int m = min(cnt - base, 32);
        for (int j = 0; j < m; j += 3) {
            int jj = j + sub;
            int   s = __shfl_sync(0xFFFFFFFFu, src, jj & 31);
            float n = __shfl_sync(0xFFFFFFFFu, nrm, jj & 31);
            if (act && jj < m) {
                uint2 v = __ldg((const uint2*)(g_h2h + (size_t)s * CLASSES) + q);
                half2* hp = (half2*)&v;
                float2 f0 = __half22float2(hp[0]);
                float2 f1 = __half22float2(hp[1]);
                acc[0] = fmaf(f0.x, n, acc[0]);
                acc[1] = fmaf(f0.y, n, acc[1]);
                acc[2] = fmaf(f1.x, n, acc[2]);
                acc[3] = fmaf(f1.y, n, acc[3]);
            }
        }
    }
#pragma unroll
    for (int k = 0; k < 4; k++) {
        float v1 = __shfl_down_sync(0xFFFFFFFFu, acc[k], 10);
        float v2 = __shfl_down_sync(0xFFFFFFFFu, acc[k], 20);
        acc[k] += v1 + v2;
    }

    if (lane < 10) {
        uint2 v = ((const uint2*)(g_h2h + (size_t)c * CLASSES))[lane];
        half2* hp = (half2*)&v;
        float2 f0 = __half22float2(hp[0]);
        float2 f1 = __half22float2(hp[1]);
        float4 b = __ldg(&((const float4*)bg2)[lane]);
        float4 o;
        o.x = fmaf(f0.x, dd, acc[0]) + b.x;
        o.y = fmaf(f0.y, dd, acc[1]) + b.y;
        o.z = fmaf(f1.x, dd, acc[2]) + b.z;
        o.w = fmaf(f1.y, dd, acc[3]) + b.w;
        ((float4*)(out2 + (size_t)c * CLASSES))[lane] = o;
    }
}

// ---------------- launch ----------------
extern "C" void kernel_launch(void* const* d_in, const int* in_sizes, int n_in,
                              void* d_out, int out_size)
{
    const float* x      = (const float*)d_in[0];
    const int*   eidx   = (const int*)d_in[1];
    const float* edge_x = (const float*)d_in[2];
    const float* W1     = (const float*)d_in[3];
    const float* b1     = (const float*)d_in[4];
    const float* W2     = (const float*)d_in[5];
    const float* b2     = (const float*)d_in[6];
    const float* Wg1    = (const float*)d_in[7];
    const float* bg1    = (const float*)d_in[8];
    const float* Wg2    = (const float*)d_in[9];
    const float* bg2    = (const float*)d_in[10];
    float*       out2   = (float*)d_out;

    k_init_detect<<<(N_NODES + 255) / 256, 256>>>(eidx, Wg1, Wg2);
    k_mlp_gemm1<<<G1_BLOCKS + MLP_BLOCKS, 256>>>(edge_x, eidx, W1, b1, W2, b2, x);
    k_dinv<<<(N_NODES + 255) / 256, 256>>>();
    k_gather1<<<(N_NODES * 32 + 255) / 256, 256>>>(bg1);
    k_gemm2<<<(N_NODES + G1_ROWS - 1) / G1_ROWS, 192>>>();
    k_gather2<<<(N_NODES * 32 + 255) / 256, 256>>>(bg2, out2);
}